// round 1
// baseline (speedup 1.0000x reference)
#include <cuda_runtime.h>
#include <math.h>

#define BB 8
#define QQ 4
#define HH 4096
#define NHEAD 32
#define NKV 8
#define HD 128
#define GG 4
#define NTOK (BB*QQ)                     // 32
#define QKV_COLS (NHEAD*HD + 2*NKV*HD)   // 6144
#define KSPLIT 16
#define KCHUNK (HH/KSPLIT)               // 256
#define NSPLIT 16
#define ATT_SCALE 0.08838834764831845f   // 1/sqrt(128)

// ---------------- device scratch (no allocations allowed) ----------------
__device__ float g_hT[HH*NTOK];                     // hidden transposed [K][32]
__device__ float g_part_qkv[KSPLIT*NTOK*QKV_COLS];  // GEMM-A partials
__device__ float g_q[NTOK*NHEAD*HD];                // rope'd q
__device__ float g_k[NTOK*NKV*HD];                  // rope'd k (new tokens)
__device__ float g_v[NTOK*NKV*HD];                  // v (new tokens)
__device__ float g_po[BB*NKV*NSPLIT*16*HD];         // attention split partial O
__device__ float g_pml[BB*NKV*NSPLIT*16*2];         // attention split (m,l)
__device__ float g_attnT[HH*NTOK];                  // attention out, transposed [col][row]
__device__ float g_part_out[KSPLIT*NTOK*HH];        // GEMM-O partials

// ---------------- packed f32x2 helpers ----------------
__device__ __forceinline__ void ffma2(unsigned long long &acc,
                                      unsigned long long a, unsigned long long b) {
    asm("fma.rn.f32x2 %0, %1, %2, %0;" : "+l"(acc) : "l"(a), "l"(b));
}
__device__ __forceinline__ unsigned long long pack2(float x, float y) {
    unsigned long long r;
    asm("mov.b64 %0, {%1, %2};" : "=l"(r)
        : "r"(__float_as_uint(x)), "r"(__float_as_uint(y)));
    return r;
}
__device__ __forceinline__ float lo2(unsigned long long u) {
    return __uint_as_float((unsigned int)(u & 0xffffffffULL));
}
__device__ __forceinline__ float hi2(unsigned long long u) {
    return __uint_as_float((unsigned int)(u >> 32));
}

// ---------------- 1. transpose hidden (32x4096 -> [4096][32]) ----------------
__global__ void k_transpose(const float* __restrict__ x) {
    int idx = blockIdx.x * 256 + threadIdx.x;     // < 131072
    int r = idx >> 12;
    int k = idx & 4095;
    g_hT[k*NTOK + r] = x[idx];
}

// ---------------- 2. QKV GEMM partial (K-split) ----------------
// grid (48, KSPLIT), block 128. Thread owns one output column, 32 token rows.
__global__ void k_gemm_qkv(const float* __restrict__ Wq,
                           const float* __restrict__ Wk,
                           const float* __restrict__ Wv) {
    __shared__ float4 hs[KCHUNK][8];   // [k][rowquad] 32 KB
    int tx = threadIdx.x;
    int col = blockIdx.x * 128 + tx;
    int k0 = blockIdx.y * KCHUNK;

    const float* wcol;
    int wstride;
    if (col < 4096)       { wcol = Wq + col;          wstride = 4096; }
    else if (col < 5120)  { wcol = Wk + (col - 4096); wstride = 1024; }
    else                  { wcol = Wv + (col - 5120); wstride = 1024; }
    wcol += (size_t)k0 * wstride;

    const float4* src = (const float4*)(g_hT + (size_t)k0 * NTOK);
    float4* dst = &hs[0][0];
    #pragma unroll
    for (int i = 0; i < 16; i++) dst[tx + 128*i] = src[tx + 128*i];
    __syncthreads();

    unsigned long long acc[16];
    #pragma unroll
    for (int i = 0; i < 16; i++) acc[i] = 0ULL;

    #pragma unroll 4
    for (int kk = 0; kk < KCHUNK; kk++) {
        float w = wcol[(size_t)kk * wstride];
        unsigned long long w2 = pack2(w, w);
        const ulonglong2* hp = (const ulonglong2*)&hs[kk][0];
        #pragma unroll
        for (int j = 0; j < 8; j++) {
            ulonglong2 h = hp[j];                 // rows 4j..4j+3 at k0+kk
            ffma2(acc[2*j],   h.x, w2);
            ffma2(acc[2*j+1], h.y, w2);
        }
    }

    float* out = g_part_qkv + (size_t)blockIdx.y * NTOK * QKV_COLS + col;
    #pragma unroll
    for (int i = 0; i < 16; i++) {
        out[(size_t)(2*i)   * QKV_COLS] = lo2(acc[i]);
        out[(size_t)(2*i+1) * QKV_COLS] = hi2(acc[i]);
    }
}

// ---------------- 3. reduce K-splits + RoPE ----------------
// grid (48 head-slots, 32 rows), block 128 (one thread per dim)
__global__ void k_reduce_rope(const float* __restrict__ cosb,
                              const float* __restrict__ sinb) {
    int slot = blockIdx.x;
    int row  = blockIdx.y;
    int d    = threadIdx.x;
    int col  = slot*128 + d;

    float s = 0.f;
    #pragma unroll
    for (int i = 0; i < KSPLIT; i++)
        s += g_part_qkv[((size_t)i*NTOK + row)*QKV_COLS + col];

    __shared__ float x[128];
    x[d] = s;
    __syncthreads();

    if (slot < 40) {     // q heads (0..31) and k heads (32..39) get RoPE
        float c  = cosb[row*128 + d];
        float sn = sinb[row*128 + d];
        float rot = (d < 64) ? -x[d + 64] : x[d - 64];
        float val = s*c + rot*sn;
        if (slot < 32) g_q[(size_t)row*4096 + col] = val;
        else           g_k[(size_t)row*1024 + (slot-32)*128 + d] = val;
    } else {             // v heads (40..47), no RoPE
        g_v[(size_t)row*1024 + (slot-40)*128 + d] = s;
    }
}

// ---------------- 4. flash-decoding attention ----------------
// grid (NSPLIT, NKV, BB), block 256
__global__ void k_attn(const float* __restrict__ Kc,
                       const float* __restrict__ Vc,
                       const int* __restrict__ cache_lens, int cap) {
    __shared__ float q_s[16][132];
    __shared__ float K_s[32][132];
    __shared__ float V_s[32][132];
    __shared__ float s_buf[16][33];
    __shared__ float m_sh[16];
    __shared__ float a_sh[16];

    int tid = threadIdx.x;
    int split = blockIdx.x, kv = blockIdx.y, b = blockIdx.z;
    int cl = cache_lens[b];
    int n_total = cl + QQ;
    int len = (n_total + NSPLIT - 1) / NSPLIT;
    int s0 = split * len;
    int s1 = min(s0 + len, n_total);

    size_t pbase = (((size_t)(b*NKV + kv))*NSPLIT + split)*16;

    int qi_p = tid >> 4;      // PV mapping: query
    int dg   = tid & 15;      // PV mapping: dim group (8 dims)
    int d0   = dg * 8;
    int qi_s = tid & 15;      // score mapping: query
    int po   = tid >> 4;      // score mapping: position lane

    if (s0 >= s1) {
        if (tid < 16) {
            g_pml[(pbase + tid)*2]     = -1e30f;
            g_pml[(pbase + tid)*2 + 1] = 0.f;
        }
        float* op = g_po + (pbase + qi_p)*HD + d0;
        #pragma unroll
        for (int j = 0; j < 8; j++) op[j] = 0.f;
        return;
    }

    // stage q for the 16 (g,qo) queries of this (b,kv)
    for (int idx = tid; idx < 16*128; idx += 256) {
        int qi = idx >> 7, d = idx & 127;
        int qo = qi >> 2, g = qi & 3;
        int row  = b*QQ + qo;
        int head = kv*GG + g;
        q_s[qi][d] = g_q[(size_t)row*4096 + head*128 + d];
    }

    float m_run = -1e30f, l_run = 0.f;
    unsigned long long oacc[4] = {0ULL, 0ULL, 0ULL, 0ULL};

    __syncthreads();

    for (int c0 = s0; c0 < s1; c0 += 32) {
        int nchunk = min(32, s1 - c0);

        // load K,V chunk (new tokens read from g_k/g_v, not the cache)
        int tf4 = nchunk * 32;
        for (int li = tid; li < tf4; li += 256) {
            int p = li >> 5, d4 = li & 31;
            int sg = c0 + p;
            float4 kval, vval;
            if (sg < cl) {
                size_t off = (((size_t)b*cap + sg)*NKV + kv)*HD + d4*4;
                kval = *(const float4*)(Kc + off);
                vval = *(const float4*)(Vc + off);
            } else {
                int row = b*QQ + (sg - cl);
                size_t off = (size_t)row*(NKV*HD) + kv*HD + d4*4;
                kval = *(const float4*)(g_k + off);
                vval = *(const float4*)(g_v + off);
            }
            *(float4*)&K_s[p][d4*4] = kval;
            *(float4*)&V_s[p][d4*4] = vval;
        }
        __syncthreads();

        // scores: thread (qi_s, po) handles positions po and po+16
        {
            const ulonglong2* qp  = (const ulonglong2*)&q_s[qi_s][0];
            const ulonglong2* kp0 = (const ulonglong2*)&K_s[po][0];
            const ulonglong2* kp1 = (const ulonglong2*)&K_s[po + 16][0];
            unsigned long long a0 = 0, a1 = 0, b0 = 0, b1 = 0;
            #pragma unroll
            for (int j = 0; j < 32; j++) {
                ulonglong2 qv = qp[j];
                ulonglong2 k0 = kp0[j];
                ulonglong2 k1 = kp1[j];
                ffma2(a0, qv.x, k0.x);
                ffma2(a1, qv.y, k0.y);
                ffma2(b0, qv.x, k1.x);
                ffma2(b1, qv.y, k1.y);
            }
            float dot0 = lo2(a0) + hi2(a0) + lo2(a1) + hi2(a1);
            float dot1 = lo2(b0) + hi2(b0) + lo2(b1) + hi2(b1);
            int qo = qi_s >> 2;
            int sg0 = c0 + po, sg1 = c0 + po + 16;
            bool v0 = (po      < nchunk) && (sg0 <= cl + qo);
            bool v1 = (po + 16 < nchunk) && (sg1 <= cl + qo);
            s_buf[qi_s][po]      = v0 ? dot0 * ATT_SCALE : -1e30f;
            s_buf[qi_s][po + 16] = v1 ? dot1 * ATT_SCALE : -1e30f;
        }
        __syncthreads();

        // running-max update (one thread per query)
        if (tid < 16) {
            float m_c = -1e30f;
            #pragma unroll
            for (int p = 0; p < 32; p++) m_c = fmaxf(m_c, s_buf[tid][p]);
            float m_new = fmaxf(m_run, m_c);
            float alpha = (m_run <= -1e29f) ? 0.f : __expf(m_run - m_new);
            m_sh[tid] = m_new;
            a_sh[tid] = alpha;
            m_run = m_new;
            l_run *= alpha;
        }
        __syncthreads();

        // exponentials (score-layout threads)
        {
            float mq  = m_sh[qi_s];
            float sc0 = s_buf[qi_s][po];
            float sc1 = s_buf[qi_s][po + 16];
            s_buf[qi_s][po]      = (sc0 <= -1e29f) ? 0.f : __expf(sc0 - mq);
            s_buf[qi_s][po + 16] = (sc1 <= -1e29f) ? 0.f : __expf(sc1 - mq);
        }
        __syncthreads();

        // l accumulation + PV
        if (tid < 16) {
            float ls = 0.f;
            #pragma unroll
            for (int p = 0; p < 32; p++) ls += s_buf[tid][p];
            l_run += ls;
        }
        {
            float alpha = a_sh[qi_p];
            unsigned long long al2 = pack2(alpha, alpha);
            #pragma unroll
            for (int i = 0; i < 4; i++)
                asm("mul.rn.f32x2 %0, %0, %1;" : "+l"(oacc[i]) : "l"(al2));
            const float* sp = &s_buf[qi_p][0];
            for (int p = 0; p < nchunk; p++) {
                float pv = sp[p];
                unsigned long long p2 = pack2(pv, pv);
                const ulonglong2* vp = (const ulonglong2*)&V_s[p][d0];
                ulonglong2 v0 = vp[0], v1 = vp[1];
                ffma2(oacc[0], p2, v0.x);
                ffma2(oacc[1], p2, v0.y);
                ffma2(oacc[2], p2, v1.x);
                ffma2(oacc[3], p2, v1.y);
            }
        }
        __syncthreads();
    }

    if (tid < 16) {
        g_pml[(pbase + tid)*2]     = m_run;
        g_pml[(pbase + tid)*2 + 1] = l_run;
    }
    float* op = g_po + (pbase + qi_p)*HD + d0;
    op[0] = lo2(oacc[0]); op[1] = hi2(oacc[0]);
    op[2] = lo2(oacc[1]); op[3] = hi2(oacc[1]);
    op[4] = lo2(oacc[2]); op[5] = hi2(oacc[2]);
    op[6] = lo2(oacc[3]); op[7] = hi2(oacc[3]);
}

// ---------------- 5. combine split-softmax partials -> attnT ----------------
// grid 64 = (b,kv), block 256 = (16 queries x 16 dim-groups)
__global__ void k_combine() {
    int bkv = blockIdx.x;
    int b = bkv >> 3, kv = bkv & 7;
    int tid = threadIdx.x;
    int qi = tid >> 4, dg = tid & 15;
    int d0 = dg * 8;
    size_t base = (size_t)bkv * NSPLIT * 16;

    float m_tot = -1e30f;
    for (int s = 0; s < NSPLIT; s++)
        m_tot = fmaxf(m_tot, g_pml[(base + s*16 + qi)*2]);

    float o[8];
    #pragma unroll
    for (int j = 0; j < 8; j++) o[j] = 0.f;
    float l_tot = 0.f;

    for (int s = 0; s < NSPLIT; s++) {
        float m = g_pml[(base + s*16 + qi)*2];
        float l = g_pml[(base + s*16 + qi)*2 + 1];
        float w = (m <= -1e29f) ? 0.f : __expf(m - m_tot);
        l_tot += w * l;
        const float4* op = (const float4*)(g_po + (base + s*16 + qi)*HD + d0);
        float4 x0 = op[0], x1 = op[1];
        o[0] += w*x0.x; o[1] += w*x0.y; o[2] += w*x0.z; o[3] += w*x0.w;
        o[4] += w*x1.x; o[5] += w*x1.y; o[6] += w*x1.z; o[7] += w*x1.w;
    }
    float inv = 1.f / l_tot;
    int qo = qi >> 2, g = qi & 3;
    int row  = b*QQ + qo;
    int head = kv*GG + g;
    #pragma unroll
    for (int j = 0; j < 8; j++)
        g_attnT[(size_t)(head*128 + d0 + j)*NTOK + row] = o[j] * inv;
}

// ---------------- 6. O GEMM partial (K-split) ----------------
// grid (32, KSPLIT), block 128
__global__ void k_gemm_o(const float* __restrict__ Wo) {
    __shared__ float4 hs[KCHUNK][8];
    int tx = threadIdx.x;
    int col = blockIdx.x * 128 + tx;
    int k0 = blockIdx.y * KCHUNK;
    const float* wcol = Wo + (size_t)k0 * 4096 + col;

    const float4* src = (const float4*)(g_attnT + (size_t)k0 * NTOK);
    float4* dst = &hs[0][0];
    #pragma unroll
    for (int i = 0; i < 16; i++) dst[tx + 128*i] = src[tx + 128*i];
    __syncthreads();

    unsigned long long acc[16];
    #pragma unroll
    for (int i = 0; i < 16; i++) acc[i] = 0ULL;

    #pragma unroll 4
    for (int kk = 0; kk < KCHUNK; kk++) {
        float w = wcol[(size_t)kk * 4096];
        unsigned long long w2 = pack2(w, w);
        const ulonglong2* hp = (const ulonglong2*)&hs[kk][0];
        #pragma unroll
        for (int j = 0; j < 8; j++) {
            ulonglong2 h = hp[j];
            ffma2(acc[2*j],   h.x, w2);
            ffma2(acc[2*j+1], h.y, w2);
        }
    }

    float* out = g_part_out + (size_t)blockIdx.y * NTOK * HH + col;
    #pragma unroll
    for (int i = 0; i < 16; i++) {
        out[(size_t)(2*i)   * HH] = lo2(acc[i]);
        out[(size_t)(2*i+1) * HH] = hi2(acc[i]);
    }
}

// ---------------- 7. reduce O partials -> output ----------------
__global__ void k_reduce_out(float* __restrict__ out) {
    int idx = blockIdx.x * 256 + threadIdx.x;   // < 131072
    float s = 0.f;
    #pragma unroll
    for (int i = 0; i < KSPLIT; i++)
        s += g_part_out[(size_t)i * NTOK * HH + idx];
    out[idx] = s;
}

// ---------------- launch ----------------
extern "C" void kernel_launch(void* const* d_in, const int* in_sizes, int n_in,
                              void* d_out, int out_size) {
    const float* hidden = (const float*)d_in[0];
    const float* cosb   = (const float*)d_in[1];
    const float* sinb   = (const float*)d_in[2];
    const float* Wq     = (const float*)d_in[3];
    const float* Wk     = (const float*)d_in[4];
    const float* Wv     = (const float*)d_in[5];
    const float* Wo     = (const float*)d_in[6];
    const float* Kc     = (const float*)d_in[7];
    const float* Vc     = (const float*)d_in[8];
    const int*   cls    = (const int*)d_in[9];
    int cap = in_sizes[7] / (BB * NKV * HD);   // 4100

    k_transpose  <<<512, 256>>>(hidden);
    k_gemm_qkv   <<<dim3(48, KSPLIT), 128>>>(Wq, Wk, Wv);
    k_reduce_rope<<<dim3(48, NTOK), 128>>>(cosb, sinb);
    k_attn       <<<dim3(NSPLIT, NKV, BB), 256>>>(Kc, Vc, cls, cap);
    k_combine    <<<64, 256>>>();
    k_gemm_o     <<<dim3(32, KSPLIT), 128>>>(Wo);
    k_reduce_out <<<512, 256>>>((float*)d_out);
}

// round 2
// speedup vs baseline: 1.2925x; 1.2925x over previous
#include <cuda_runtime.h>
#include <math.h>

#define BB 8
#define QQ 4
#define HH 4096
#define NHEAD 32
#define NKV 8
#define HD 128
#define GG 4
#define NTOK (BB*QQ)                     // 32
#define QKV_COLS (NHEAD*HD + 2*NKV*HD)   // 6144
#define KSPLIT 16
#define KCHUNK (HH/KSPLIT)               // 256
#define NSPLIT 16
#define ATT_SCALE 0.08838834764831845f   // 1/sqrt(128)

#define PAD_K 132
#define PAD_V 136
#define PAD_S 36

// ---------------- device scratch (no allocations allowed) ----------------
__device__ float g_hT[HH*NTOK];                     // hidden transposed [K][32]
__device__ float g_part_qkv[KSPLIT*NTOK*QKV_COLS];  // GEMM-A partials
__device__ float g_q[NTOK*NHEAD*HD];                // rope'd q
__device__ float g_k[NTOK*NKV*HD];                  // rope'd k (new tokens)
__device__ float g_v[NTOK*NKV*HD];                  // v (new tokens)
__device__ float g_po[BB*NKV*NSPLIT*16*HD];         // attention split partial O
__device__ float g_pml[BB*NKV*NSPLIT*16*2];         // attention split (m,l)
__device__ float g_attnT[HH*NTOK];                  // attention out, transposed
__device__ float g_part_out[KSPLIT*NTOK*HH];        // GEMM-O partials

// ---------------- packed f32x2 helpers ----------------
__device__ __forceinline__ void ffma2(unsigned long long &acc,
                                      unsigned long long a, unsigned long long b) {
    asm("fma.rn.f32x2 %0, %1, %2, %0;" : "+l"(acc) : "l"(a), "l"(b));
}
__device__ __forceinline__ unsigned long long pack2(float x, float y) {
    unsigned long long r;
    asm("mov.b64 %0, {%1, %2};" : "=l"(r)
        : "r"(__float_as_uint(x)), "r"(__float_as_uint(y)));
    return r;
}
__device__ __forceinline__ float lo2(unsigned long long u) {
    return __uint_as_float((unsigned int)(u & 0xffffffffULL));
}
__device__ __forceinline__ float hi2(unsigned long long u) {
    return __uint_as_float((unsigned int)(u >> 32));
}

// ---------------- tf32 helpers ----------------
__device__ __forceinline__ float tf32r(float x) {
    unsigned u;
    asm("cvt.rna.tf32.f32 %0, %1;" : "=r"(u) : "f"(x));
    return __uint_as_float(u);
}
__device__ __forceinline__ void mma_tf32(float& d0, float& d1, float& d2, float& d3,
                                         float a0, float a1, float a2, float a3,
                                         float b0, float b1) {
    asm volatile(
        "mma.sync.aligned.m16n8k8.row.col.f32.tf32.tf32.f32 "
        "{%0,%1,%2,%3}, {%4,%5,%6,%7}, {%8,%9}, {%0,%1,%2,%3};"
        : "+f"(d0), "+f"(d1), "+f"(d2), "+f"(d3)
        : "r"(__float_as_uint(a0)), "r"(__float_as_uint(a1)),
          "r"(__float_as_uint(a2)), "r"(__float_as_uint(a3)),
          "r"(__float_as_uint(b0)), "r"(__float_as_uint(b1)));
}

// ---------------- 1. transpose hidden ----------------
__global__ void k_transpose(const float* __restrict__ x) {
    int idx = blockIdx.x * 256 + threadIdx.x;
    int r = idx >> 12;
    int k = idx & 4095;
    g_hT[k*NTOK + r] = x[idx];
}

// ---------------- 2. QKV GEMM partial (K-split) ----------------
__global__ void k_gemm_qkv(const float* __restrict__ Wq,
                           const float* __restrict__ Wk,
                           const float* __restrict__ Wv) {
    __shared__ float4 hs[KCHUNK][8];
    int tx = threadIdx.x;
    int col = blockIdx.x * 128 + tx;
    int k0 = blockIdx.y * KCHUNK;

    const float* wcol;
    int wstride;
    if (col < 4096)       { wcol = Wq + col;          wstride = 4096; }
    else if (col < 5120)  { wcol = Wk + (col - 4096); wstride = 1024; }
    else                  { wcol = Wv + (col - 5120); wstride = 1024; }
    wcol += (size_t)k0 * wstride;

    const float4* src = (const float4*)(g_hT + (size_t)k0 * NTOK);
    float4* dst = &hs[0][0];
    #pragma unroll
    for (int i = 0; i < 16; i++) dst[tx + 128*i] = src[tx + 128*i];
    __syncthreads();

    unsigned long long acc[16];
    #pragma unroll
    for (int i = 0; i < 16; i++) acc[i] = 0ULL;

    #pragma unroll 4
    for (int kk = 0; kk < KCHUNK; kk++) {
        float w = wcol[(size_t)kk * wstride];
        unsigned long long w2 = pack2(w, w);
        const ulonglong2* hp = (const ulonglong2*)&hs[kk][0];
        #pragma unroll
        for (int j = 0; j < 8; j++) {
            ulonglong2 h = hp[j];
            ffma2(acc[2*j],   h.x, w2);
            ffma2(acc[2*j+1], h.y, w2);
        }
    }

    float* out = g_part_qkv + (size_t)blockIdx.y * NTOK * QKV_COLS + col;
    #pragma unroll
    for (int i = 0; i < 16; i++) {
        out[(size_t)(2*i)   * QKV_COLS] = lo2(acc[i]);
        out[(size_t)(2*i+1) * QKV_COLS] = hi2(acc[i]);
    }
}

// ---------------- 3. reduce K-splits + RoPE ----------------
__global__ void k_reduce_rope(const float* __restrict__ cosb,
                              const float* __restrict__ sinb) {
    int slot = blockIdx.x;
    int row  = blockIdx.y;
    int d    = threadIdx.x;
    int col  = slot*128 + d;

    float s = 0.f;
    #pragma unroll
    for (int i = 0; i < KSPLIT; i++)
        s += g_part_qkv[((size_t)i*NTOK + row)*QKV_COLS + col];

    __shared__ float x[128];
    x[d] = s;
    __syncthreads();

    if (slot < 40) {
        float c  = cosb[row*128 + d];
        float sn = sinb[row*128 + d];
        float rot = (d < 64) ? -x[d + 64] : x[d - 64];
        float val = s*c + rot*sn;
        if (slot < 32) g_q[(size_t)row*4096 + col] = val;
        else           g_k[(size_t)row*1024 + (slot-32)*128 + d] = val;
    } else {
        g_v[(size_t)row*1024 + (slot-40)*128 + d] = s;
    }
}

// ---------------- 4. flash-decoding attention (tf32 mma) ----------------
// grid (NSPLIT, NKV, BB), block 128 (4 warps)
// per chunk of 32 positions:
//   scores: warp w -> S tile [16 q][8 pos] via 16x m16n8k8 over the 128 dims
//   PV:     warp w -> O tile [16 q][32 dims] via 4 ksteps x 4 ntiles
__global__ void __launch_bounds__(128) k_attn(const float* __restrict__ Kc,
                       const float* __restrict__ Vc,
                       const int* __restrict__ cache_lens, int cap) {
    __shared__ float K_s[32][PAD_K];
    __shared__ float V_s[32][PAD_V];
    __shared__ float q_s[16][PAD_K];
    __shared__ float s_buf[16][PAD_S];
    __shared__ float m_sh[16];
    __shared__ float a_sh[16];

    int tid  = threadIdx.x;
    int warp = tid >> 5;
    int lane = tid & 31;
    int g    = lane >> 2;     // groupID
    int t    = lane & 3;      // threadID_in_group

    int split = blockIdx.x, kvh = blockIdx.y, b = blockIdx.z;
    int cl = cache_lens[b];
    int n_total = cl + QQ;
    int len = (n_total + NSPLIT - 1) / NSPLIT;
    int s0 = split * len;
    int s1 = min(s0 + len, n_total);

    size_t pbase = (((size_t)(b*NKV + kvh))*NSPLIT + split)*16;

    if (s0 >= s1) {
        if (tid < 16) {
            g_pml[(pbase + tid)*2]     = -1e30f;
            g_pml[(pbase + tid)*2 + 1] = 0.f;
        }
        for (int i = tid; i < 16*HD; i += 128)
            g_po[pbase*HD + i] = 0.f;
        return;
    }

    // stage q (tf32-rounded)
    for (int i = tid; i < 16*128; i += 128) {
        int qi = i >> 7, d = i & 127;
        int row  = b*QQ + (qi >> 2);
        int head = kvh*GG + (qi & 3);
        q_s[qi][d] = tf32r(g_q[(size_t)row*4096 + head*128 + d]);
    }

    float m_run = -1e30f, l_run = 0.f;
    float oacc[4][4];
    #pragma unroll
    for (int nt = 0; nt < 4; nt++)
        #pragma unroll
        for (int j = 0; j < 4; j++) oacc[nt][j] = 0.f;

    for (int c0 = s0; c0 < s1; c0 += 32) {
        __syncthreads();   // prev PV done before staging overwrites K_s/V_s/s_buf

        // ---- stage K/V chunk (tf32-rounded, zero-fill past s1) ----
        #pragma unroll
        for (int i = 0; i < 8; i++) {
            int idx = tid + i*128;          // 1024 float4 per matrix
            int p  = idx >> 5;
            int f4 = idx & 31;
            int sg = c0 + p;
            float4 kv4 = make_float4(0.f,0.f,0.f,0.f);
            float4 vv4 = make_float4(0.f,0.f,0.f,0.f);
            if (sg < s1) {
                if (sg < cl) {
                    size_t off = (((size_t)b*cap + sg)*NKV + kvh)*HD + f4*4;
                    kv4 = *(const float4*)(Kc + off);
                    vv4 = *(const float4*)(Vc + off);
                } else {
                    int row = b*QQ + (sg - cl);
                    size_t off = (size_t)row*(NKV*HD) + kvh*HD + f4*4;
                    kv4 = *(const float4*)(g_k + off);
                    vv4 = *(const float4*)(g_v + off);
                }
            }
            kv4.x = tf32r(kv4.x); kv4.y = tf32r(kv4.y);
            kv4.z = tf32r(kv4.z); kv4.w = tf32r(kv4.w);
            vv4.x = tf32r(vv4.x); vv4.y = tf32r(vv4.y);
            vv4.z = tf32r(vv4.z); vv4.w = tf32r(vv4.w);
            *(float4*)&K_s[p][f4*4] = kv4;
            *(float4*)&V_s[p][f4*4] = vv4;
        }
        __syncthreads();

        // ---- scores: warp w computes S[16][8] for positions p0..p0+7 ----
        {
            int p0 = warp * 8;
            float c0r = 0.f, c1r = 0.f, c2r = 0.f, c3r = 0.f;
            #pragma unroll
            for (int ks = 0; ks < 16; ks++) {
                int kb = ks * 8;
                float a0 = q_s[g  ][kb + t];
                float a1 = q_s[g+8][kb + t];
                float a2 = q_s[g  ][kb + t + 4];
                float a3 = q_s[g+8][kb + t + 4];
                float b0 = K_s[p0 + g][kb + t];
                float b1 = K_s[p0 + g][kb + t + 4];
                mma_tf32(c0r, c1r, c2r, c3r, a0, a1, a2, a3, b0, b1);
            }
            s_buf[g  ][p0 + 2*t    ] = c0r;
            s_buf[g  ][p0 + 2*t + 1] = c1r;
            s_buf[g+8][p0 + 2*t    ] = c2r;
            s_buf[g+8][p0 + 2*t + 1] = c3r;
        }
        __syncthreads();

        // ---- running max / alpha (threads 0..15 = query rows) ----
        if (tid < 16) {
            int L = min(s1, cl + (tid >> 2) + 1) - c0;  // valid positions this chunk
            float m_c = -1e30f;
            for (int p = 0; p < 32; p++)
                if (p < L) m_c = fmaxf(m_c, s_buf[tid][p] * ATT_SCALE);
            float m_new = fmaxf(m_run, m_c);
            float alpha = __expf(m_run - m_new);
            m_sh[tid] = m_new;
            a_sh[tid] = alpha;
            m_run = m_new;
            l_run *= alpha;
        }
        __syncthreads();

        // ---- exp + tf32 round (128 threads x 4 elems) ----
        {
            int qi = tid & 15;
            int pb = (tid >> 4) * 4;
            int L = min(s1, cl + (qi >> 2) + 1) - c0;
            float mq = m_sh[qi];
            #pragma unroll
            for (int j = 0; j < 4; j++) {
                int p = pb + j;
                float val = s_buf[qi][p];
                float r = (p < L) ? __expf(val * ATT_SCALE - mq) : 0.f;
                s_buf[qi][p] = tf32r(r);
            }
        }
        __syncthreads();

        // ---- l accumulation ----
        if (tid < 16) {
            float ls = 0.f;
            #pragma unroll
            for (int p = 0; p < 32; p++) ls += s_buf[tid][p];
            l_run += ls;
        }

        // ---- PV: O = O*alpha + P @ V ----
        {
            float al0 = a_sh[g];
            float al1 = a_sh[g+8];
            #pragma unroll
            for (int nt = 0; nt < 4; nt++) {
                oacc[nt][0] *= al0; oacc[nt][1] *= al0;
                oacc[nt][2] *= al1; oacc[nt][3] *= al1;
            }
            #pragma unroll
            for (int ks = 0; ks < 4; ks++) {
                int kb = ks * 8;
                float a0 = s_buf[g  ][kb + t];
                float a1 = s_buf[g+8][kb + t];
                float a2 = s_buf[g  ][kb + t + 4];
                float a3 = s_buf[g+8][kb + t + 4];
                #pragma unroll
                for (int nt = 0; nt < 4; nt++) {
                    int n0 = warp*32 + nt*8;
                    float b0 = V_s[kb + t    ][n0 + g];
                    float b1 = V_s[kb + t + 4][n0 + g];
                    mma_tf32(oacc[nt][0], oacc[nt][1], oacc[nt][2], oacc[nt][3],
                             a0, a1, a2, a3, b0, b1);
                }
            }
        }
    }

    if (tid < 16) {
        g_pml[(pbase + tid)*2]     = m_run;
        g_pml[(pbase + tid)*2 + 1] = l_run;
    }
    #pragma unroll
    for (int nt = 0; nt < 4; nt++) {
        int col = warp*32 + nt*8 + 2*t;
        *(float2*)(g_po + (pbase + g    )*HD + col) = make_float2(oacc[nt][0], oacc[nt][1]);
        *(float2*)(g_po + (pbase + g + 8)*HD + col) = make_float2(oacc[nt][2], oacc[nt][3]);
    }
}

// ---------------- 5. combine split-softmax partials -> attnT ----------------
__global__ void k_combine() {
    int bkv = blockIdx.x;
    int b = bkv >> 3, kv = bkv & 7;
    int tid = threadIdx.x;
    int qi = tid >> 4, dg = tid & 15;
    int d0 = dg * 8;
    size_t base = (size_t)bkv * NSPLIT * 16;

    float m_tot = -1e30f;
    for (int s = 0; s < NSPLIT; s++)
        m_tot = fmaxf(m_tot, g_pml[(base + s*16 + qi)*2]);

    float o[8];
    #pragma unroll
    for (int j = 0; j < 8; j++) o[j] = 0.f;
    float l_tot = 0.f;

    for (int s = 0; s < NSPLIT; s++) {
        float m = g_pml[(base + s*16 + qi)*2];
        float l = g_pml[(base + s*16 + qi)*2 + 1];
        float w = (m <= -1e29f) ? 0.f : __expf(m - m_tot);
        l_tot += w * l;
        const float4* op = (const float4*)(g_po + (base + s*16 + qi)*HD + d0);
        float4 x0 = op[0], x1 = op[1];
        o[0] += w*x0.x; o[1] += w*x0.y; o[2] += w*x0.z; o[3] += w*x0.w;
        o[4] += w*x1.x; o[5] += w*x1.y; o[6] += w*x1.z; o[7] += w*x1.w;
    }
    float inv = 1.f / l_tot;
    int qo = qi >> 2, g = qi & 3;
    int row  = b*QQ + qo;
    int head = kv*GG + g;
    #pragma unroll
    for (int j = 0; j < 8; j++)
        g_attnT[(size_t)(head*128 + d0 + j)*NTOK + row] = o[j] * inv;
}

// ---------------- 6. O GEMM partial (K-split) ----------------
__global__ void k_gemm_o(const float* __restrict__ Wo) {
    __shared__ float4 hs[KCHUNK][8];
    int tx = threadIdx.x;
    int col = blockIdx.x * 128 + tx;
    int k0 = blockIdx.y * KCHUNK;
    const float* wcol = Wo + (size_t)k0 * 4096 + col;

    const float4* src = (const float4*)(g_attnT + (size_t)k0 * NTOK);
    float4* dst = &hs[0][0];
    #pragma unroll
    for (int i = 0; i < 16; i++) dst[tx + 128*i] = src[tx + 128*i];
    __syncthreads();

    unsigned long long acc[16];
    #pragma unroll
    for (int i = 0; i < 16; i++) acc[i] = 0ULL;

    #pragma unroll 4
    for (int kk = 0; kk < KCHUNK; kk++) {
        float w = wcol[(size_t)kk * 4096];
        unsigned long long w2 = pack2(w, w);
        const ulonglong2* hp = (const ulonglong2*)&hs[kk][0];
        #pragma unroll
        for (int j = 0; j < 8; j++) {
            ulonglong2 h = hp[j];
            ffma2(acc[2*j],   h.x, w2);
            ffma2(acc[2*j+1], h.y, w2);
        }
    }

    float* out = g_part_out + (size_t)blockIdx.y * NTOK * HH + col;
    #pragma unroll
    for (int i = 0; i < 16; i++) {
        out[(size_t)(2*i)   * HH] = lo2(acc[i]);
        out[(size_t)(2*i+1) * HH] = hi2(acc[i]);
    }
}

// ---------------- 7. reduce O partials -> output ----------------
__global__ void k_reduce_out(float* __restrict__ out) {
    int idx = blockIdx.x * 256 + threadIdx.x;
    float s = 0.f;
    #pragma unroll
    for (int i = 0; i < KSPLIT; i++)
        s += g_part_out[(size_t)i * NTOK * HH + idx];
    out[idx] = s;
}

// ---------------- launch ----------------
extern "C" void kernel_launch(void* const* d_in, const int* in_sizes, int n_in,
                              void* d_out, int out_size) {
    const float* hidden = (const float*)d_in[0];
    const float* cosb   = (const float*)d_in[1];
    const float* sinb   = (const float*)d_in[2];
    const float* Wq     = (const float*)d_in[3];
    const float* Wk     = (const float*)d_in[4];
    const float* Wv     = (const float*)d_in[5];
    const float* Wo     = (const float*)d_in[6];
    const float* Kc     = (const float*)d_in[7];
    const float* Vc     = (const float*)d_in[8];
    const int*   cls    = (const int*)d_in[9];
    int cap = in_sizes[7] / (BB * NKV * HD);   // 4100

    k_transpose  <<<512, 256>>>(hidden);
    k_gemm_qkv   <<<dim3(48, KSPLIT), 128>>>(Wq, Wk, Wv);
    k_reduce_rope<<<dim3(48, NTOK), 128>>>(cosb, sinb);
    k_attn       <<<dim3(NSPLIT, NKV, BB), 128>>>(Kc, Vc, cls, cap);
    k_combine    <<<64, 256>>>();
    k_gemm_o     <<<dim3(32, KSPLIT), 128>>>(Wo);
    k_reduce_out <<<512, 256>>>((float*)d_out);
}

// round 3
// speedup vs baseline: 2.1122x; 1.6342x over previous
#include <cuda_runtime.h>
#include <math.h>

#define BB 8
#define QQ 4
#define HH 4096
#define NHEAD 32
#define NKV 8
#define HD 128
#define GG 4
#define NTOK (BB*QQ)                     // 32
#define QKV_COLS (NHEAD*HD + 2*NKV*HD)   // 6144
#define KSPLIT 32
#define KCHUNK (HH/KSPLIT)               // 128
#define NSPLIT 16
#define ATT_SCALE 0.08838834764831845f   // 1/sqrt(128)

#define PAD_K 132
#define PAD_V 136
#define PAD_S 36

// dynamic smem layout for k_attn (floats)
#define OFF_V (2*32*PAD_K)               // 8448
#define OFF_Q (OFF_V + 2*32*PAD_V)       // 17152
#define OFF_S (OFF_Q + 16*PAD_K)         // 19264
#define OFF_A (OFF_S + 16*PAD_S)         // 19840
#define SMEM_ATTN_BYTES ((OFF_A + 16)*4) // 79424

// ---------------- device scratch (no allocations allowed) ----------------
__device__ float g_hT[HH*NTOK];
__device__ float g_part_qkv[KSPLIT*NTOK*QKV_COLS];
__device__ float g_q[NTOK*NHEAD*HD];
__device__ float g_k[NTOK*NKV*HD];
__device__ float g_v[NTOK*NKV*HD];
__device__ float g_po[BB*NKV*NSPLIT*16*HD];
__device__ float g_pml[BB*NKV*NSPLIT*16*2];
__device__ float g_attnT[HH*NTOK];
__device__ float g_part_out[KSPLIT*NTOK*HH];

// ---------------- packed f32x2 helpers ----------------
__device__ __forceinline__ void ffma2(unsigned long long &acc,
                                      unsigned long long a, unsigned long long b) {
    asm("fma.rn.f32x2 %0, %1, %2, %0;" : "+l"(acc) : "l"(a), "l"(b));
}
__device__ __forceinline__ unsigned long long pack2(float x, float y) {
    unsigned long long r;
    asm("mov.b64 %0, {%1, %2};" : "=l"(r)
        : "r"(__float_as_uint(x)), "r"(__float_as_uint(y)));
    return r;
}
__device__ __forceinline__ float lo2(unsigned long long u) {
    return __uint_as_float((unsigned int)(u & 0xffffffffULL));
}
__device__ __forceinline__ float hi2(unsigned long long u) {
    return __uint_as_float((unsigned int)(u >> 32));
}

// ---------------- tf32 / mma helpers ----------------
__device__ __forceinline__ float tf32r(float x) {
    unsigned u;
    asm("cvt.rna.tf32.f32 %0, %1;" : "=r"(u) : "f"(x));
    return __uint_as_float(u);
}
__device__ __forceinline__ void mma_tf32(float& d0, float& d1, float& d2, float& d3,
                                         float a0, float a1, float a2, float a3,
                                         float b0, float b1) {
    asm volatile(
        "mma.sync.aligned.m16n8k8.row.col.f32.tf32.tf32.f32 "
        "{%0,%1,%2,%3}, {%4,%5,%6,%7}, {%8,%9}, {%0,%1,%2,%3};"
        : "+f"(d0), "+f"(d1), "+f"(d2), "+f"(d3)
        : "r"(__float_as_uint(a0)), "r"(__float_as_uint(a1)),
          "r"(__float_as_uint(a2)), "r"(__float_as_uint(a3)),
          "r"(__float_as_uint(b0)), "r"(__float_as_uint(b1)));
}

// ---------------- cp.async helpers ----------------
__device__ __forceinline__ void cp16(float* dstp, const float* src, int bytes) {
    unsigned d = (unsigned)__cvta_generic_to_shared(dstp);
    asm volatile("cp.async.cg.shared.global [%0], [%1], 16, %2;"
                 :: "r"(d), "l"(src), "r"(bytes));
}
#define CP_COMMIT() asm volatile("cp.async.commit_group;")

// ---------------- 1. transpose hidden ----------------
__global__ void k_transpose(const float* __restrict__ x) {
    int idx = blockIdx.x * 256 + threadIdx.x;
    int r = idx >> 12;
    int k = idx & 4095;
    g_hT[k*NTOK + r] = x[idx];
}

// ---------------- 2. QKV GEMM partial (K-split, MLP=8 prefetch) ----------------
__global__ void k_gemm_qkv(const float* __restrict__ Wq,
                           const float* __restrict__ Wk,
                           const float* __restrict__ Wv) {
    __shared__ float4 hs[KCHUNK][8];   // 16 KB
    int tx = threadIdx.x;
    int col = blockIdx.x * 128 + tx;
    int k0 = blockIdx.y * KCHUNK;

    const float* wcol;
    int wstride;
    if (col < 4096)       { wcol = Wq + col;          wstride = 4096; }
    else if (col < 5120)  { wcol = Wk + (col - 4096); wstride = 1024; }
    else                  { wcol = Wv + (col - 5120); wstride = 1024; }
    wcol += (size_t)k0 * wstride;

    const float4* src = (const float4*)(g_hT + (size_t)k0 * NTOK);
    float4* dst = &hs[0][0];
    #pragma unroll
    for (int i = 0; i < 8; i++) dst[tx + 128*i] = src[tx + 128*i];
    __syncthreads();

    unsigned long long acc[16];
    #pragma unroll
    for (int i = 0; i < 16; i++) acc[i] = 0ULL;

    #pragma unroll 1
    for (int kk = 0; kk < KCHUNK; kk += 8) {
        float w[8];
        #pragma unroll
        for (int u = 0; u < 8; u++) w[u] = wcol[(size_t)(kk + u) * wstride];
        #pragma unroll
        for (int u = 0; u < 8; u++) {
            unsigned long long w2 = pack2(w[u], w[u]);
            const ulonglong2* hp = (const ulonglong2*)&hs[kk + u][0];
            #pragma unroll
            for (int j = 0; j < 8; j++) {
                ulonglong2 h = hp[j];
                ffma2(acc[2*j],   h.x, w2);
                ffma2(acc[2*j+1], h.y, w2);
            }
        }
    }

    float* out = g_part_qkv + (size_t)blockIdx.y * NTOK * QKV_COLS + col;
    #pragma unroll
    for (int i = 0; i < 16; i++) {
        out[(size_t)(2*i)   * QKV_COLS] = lo2(acc[i]);
        out[(size_t)(2*i+1) * QKV_COLS] = hi2(acc[i]);
    }
}

// ---------------- 3. reduce K-splits + RoPE ----------------
__global__ void k_reduce_rope(const float* __restrict__ cosb,
                              const float* __restrict__ sinb) {
    int slot = blockIdx.x;
    int row  = blockIdx.y;
    int d    = threadIdx.x;
    int col  = slot*128 + d;

    float s = 0.f;
    #pragma unroll
    for (int i = 0; i < KSPLIT; i++)
        s += g_part_qkv[((size_t)i*NTOK + row)*QKV_COLS + col];

    __shared__ float x[128];
    x[d] = s;
    __syncthreads();

    if (slot < 40) {
        float c  = cosb[row*128 + d];
        float sn = sinb[row*128 + d];
        float rot = (d < 64) ? -x[d + 64] : x[d - 64];
        float val = s*c + rot*sn;
        if (slot < 32) g_q[(size_t)row*4096 + col] = val;
        else           g_k[(size_t)row*1024 + (slot-32)*128 + d] = val;
    } else {
        g_v[(size_t)row*1024 + (slot-40)*128 + d] = s;
    }
}

// ---------------- 4. attention: cp.async double-buffered tf32-mma flash ----------------
__device__ __forceinline__ void stage_kv(float* Ksm, float* Vsm, int bf,
        int c0, int cl, int s1, int b, int kvh, int cap,
        const float* Kc, const float* Vc, int tid) {
    #pragma unroll
    for (int i = 0; i < 16; i++) {
        int idx = tid + (i & 7) * 128;    // 1024 float4 per matrix
        int p  = idx >> 5;
        int f4 = idx & 31;
        int sg = c0 + p;
        bool isV = (i >= 8);
        const float* src;
        int bytes = 16;
        if (sg < cl) {
            src = (isV ? Vc : Kc) + ((((size_t)b*cap + sg)*NKV + kvh)*HD + f4*4);
        } else if (sg < s1) {
            int row = b*QQ + (sg - cl);
            src = (isV ? g_v : g_k) + ((size_t)row*(NKV*HD) + kvh*HD + f4*4);
        } else {
            src = Kc;           // valid dummy; src-size 0 -> zero-fill
            bytes = 0;
        }
        float* dstp = isV ? (Vsm + (size_t)bf*32*PAD_V + p*PAD_V + f4*4)
                          : (Ksm + (size_t)bf*32*PAD_K + p*PAD_K + f4*4);
        cp16(dstp, src, bytes);
    }
}

__global__ void __launch_bounds__(128) k_attn(const float* __restrict__ Kc,
                       const float* __restrict__ Vc,
                       const int* __restrict__ cache_lens, int cap) {
    extern __shared__ float sm[];
    float* Ksm = sm;             // [2][32][PAD_K]
    float* Vsm = sm + OFF_V;     // [2][32][PAD_V]
    float* qsm = sm + OFF_Q;     // [16][PAD_K]
    float* sbf = sm + OFF_S;     // [16][PAD_S]
    float* ash = sm + OFF_A;     // [16]

    int tid  = threadIdx.x;
    int warp = tid >> 5;
    int lane = tid & 31;
    int g    = lane >> 2;
    int t    = lane & 3;
    int srow = tid >> 3;          // softmax row (query index 0..15)
    int sl   = tid & 7;           // softmax lane within row

    int split = blockIdx.x, kvh = blockIdx.y, b = blockIdx.z;
    int cl = cache_lens[b];
    int n_total = cl + QQ;
    int len = (n_total + NSPLIT - 1) / NSPLIT;
    int s0 = split * len;
    int s1 = min(s0 + len, n_total);
    size_t pbase = (((size_t)(b*NKV + kvh))*NSPLIT + split)*16;

    if (s0 >= s1) {
        if (tid < 16) {
            g_pml[(pbase + tid)*2]     = -1e30f;
            g_pml[(pbase + tid)*2 + 1] = 0.f;
        }
        for (int i = tid; i < 16*HD; i += 128)
            g_po[pbase*HD + i] = 0.f;
        return;
    }

    // stage q (tf32-rounded)
    for (int i = tid; i < 16*128; i += 128) {
        int qi = i >> 7, d = i & 127;
        int row  = b*QQ + (qi >> 2);
        int head = kvh*GG + (qi & 3);
        qsm[qi*PAD_K + d] = tf32r(g_q[(size_t)row*4096 + head*128 + d]);
    }

    float m_run = -1e30f, l_run = 0.f;
    float oacc[4][4];
    #pragma unroll
    for (int nt = 0; nt < 4; nt++)
        #pragma unroll
        for (int j = 0; j < 4; j++) oacc[nt][j] = 0.f;

    int nch = (s1 - s0 + 31) >> 5;

    stage_kv(Ksm, Vsm, 0, s0, cl, s1, b, kvh, cap, Kc, Vc, tid);
    CP_COMMIT();

    for (int ci = 0; ci < nch; ci++) {
        int c0 = s0 + ci*32;
        int bf = ci & 1;

        if (ci + 1 < nch) {
            stage_kv(Ksm, Vsm, bf ^ 1, c0 + 32, cl, s1, b, kvh, cap, Kc, Vc, tid);
            CP_COMMIT();
            asm volatile("cp.async.wait_group 1;");
        } else {
            asm volatile("cp.async.wait_group 0;");
        }
        __syncthreads();

        // ---- scores: warp computes S[16][8] for positions warp*8.. ----
        {
            int p0 = warp * 8;
            const float* Kb = Ksm + (size_t)bf*32*PAD_K + (p0 + g)*PAD_K;
            float c0r = 0.f, c1r = 0.f, c2r = 0.f, c3r = 0.f;
            #pragma unroll
            for (int ks = 0; ks < 16; ks++) {
                int kb = ks * 8;
                float a0 = qsm[g*PAD_K + kb + t];
                float a1 = qsm[(g+8)*PAD_K + kb + t];
                float a2 = qsm[g*PAD_K + kb + t + 4];
                float a3 = qsm[(g+8)*PAD_K + kb + t + 4];
                float b0 = tf32r(Kb[kb + t]);
                float b1 = tf32r(Kb[kb + t + 4]);
                mma_tf32(c0r, c1r, c2r, c3r, a0, a1, a2, a3, b0, b1);
            }
            sbf[g*PAD_S     + p0 + 2*t    ] = c0r;
            sbf[g*PAD_S     + p0 + 2*t + 1] = c1r;
            sbf[(g+8)*PAD_S + p0 + 2*t    ] = c2r;
            sbf[(g+8)*PAD_S + p0 + 2*t + 1] = c3r;
        }
        __syncthreads();

        // ---- fused softmax: 16 rows x 8 lanes, shfl reductions ----
        {
            int L = min(s1, cl + (srow >> 2) + 1) - c0;  // valid count this chunk
            float sv[4];
            float m_c = -1e30f;
            #pragma unroll
            for (int j = 0; j < 4; j++) {
                int p = sl*4 + j;
                sv[j] = sbf[srow*PAD_S + p] * ATT_SCALE;
                if (p < L) m_c = fmaxf(m_c, sv[j]);
            }
            #pragma unroll
            for (int o = 4; o; o >>= 1)
                m_c = fmaxf(m_c, __shfl_xor_sync(0xffffffffu, m_c, o, 8));
            float m_new = fmaxf(m_run, m_c);
            float alpha = __expf(m_run - m_new);
            if (sl == 0) ash[srow] = alpha;
            float ls = 0.f;
            #pragma unroll
            for (int j = 0; j < 4; j++) {
                int p = sl*4 + j;
                float e = (p < L) ? __expf(sv[j] - m_new) : 0.f;
                sbf[srow*PAD_S + p] = tf32r(e);
                ls += e;
            }
            #pragma unroll
            for (int o = 4; o; o >>= 1)
                ls += __shfl_xor_sync(0xffffffffu, ls, o, 8);
            l_run = l_run * alpha + ls;
            m_run = m_new;
        }
        __syncthreads();

        // ---- PV: O = O*alpha + P @ V ----
        {
            float al0 = ash[g];
            float al1 = ash[g+8];
            #pragma unroll
            for (int nt = 0; nt < 4; nt++) {
                oacc[nt][0] *= al0; oacc[nt][1] *= al0;
                oacc[nt][2] *= al1; oacc[nt][3] *= al1;
            }
            const float* Vb = Vsm + (size_t)bf*32*PAD_V;
            #pragma unroll
            for (int ks = 0; ks < 4; ks++) {
                int kb = ks * 8;
                float a0 = sbf[g*PAD_S     + kb + t];
                float a1 = sbf[(g+8)*PAD_S + kb + t];
                float a2 = sbf[g*PAD_S     + kb + t + 4];
                float a3 = sbf[(g+8)*PAD_S + kb + t + 4];
                #pragma unroll
                for (int nt = 0; nt < 4; nt++) {
                    int n0 = warp*32 + nt*8;
                    float b0 = tf32r(Vb[(kb + t    )*PAD_V + n0 + g]);
                    float b1 = tf32r(Vb[(kb + t + 4)*PAD_V + n0 + g]);
                    mma_tf32(oacc[nt][0], oacc[nt][1], oacc[nt][2], oacc[nt][3],
                             a0, a1, a2, a3, b0, b1);
                }
            }
        }
        __syncthreads();   // protect buffers + sbf before next stage/score
    }

    if (sl == 0) {
        g_pml[(pbase + srow)*2]     = m_run;
        g_pml[(pbase + srow)*2 + 1] = l_run;
    }
    #pragma unroll
    for (int nt = 0; nt < 4; nt++) {
        int col = warp*32 + nt*8 + 2*t;
        *(float2*)(g_po + (pbase + g    )*HD + col) = make_float2(oacc[nt][0], oacc[nt][1]);
        *(float2*)(g_po + (pbase + g + 8)*HD + col) = make_float2(oacc[nt][2], oacc[nt][3]);
    }
}

// ---------------- 5. combine split-softmax partials -> attnT ----------------
__global__ void k_combine() {
    int bkv = blockIdx.x;
    int b = bkv >> 3, kv = bkv & 7;
    int tid = threadIdx.x;
    int qi = tid >> 4, dg = tid & 15;
    int d0 = dg * 8;
    size_t base = (size_t)bkv * NSPLIT * 16;

    float m_tot = -1e30f;
    for (int s = 0; s < NSPLIT; s++)
        m_tot = fmaxf(m_tot, g_pml[(base + s*16 + qi)*2]);

    float o[8];
    #pragma unroll
    for (int j = 0; j < 8; j++) o[j] = 0.f;
    float l_tot = 0.f;

    for (int s = 0; s < NSPLIT; s++) {
        float m = g_pml[(base + s*16 + qi)*2];
        float l = g_pml[(base + s*16 + qi)*2 + 1];
        float w = (m <= -1e29f) ? 0.f : __expf(m - m_tot);
        l_tot += w * l;
        const float4* op = (const float4*)(g_po + (base + s*16 + qi)*HD + d0);
        float4 x0 = op[0], x1 = op[1];
        o[0] += w*x0.x; o[1] += w*x0.y; o[2] += w*x0.z; o[3] += w*x0.w;
        o[4] += w*x1.x; o[5] += w*x1.y; o[6] += w*x1.z; o[7] += w*x1.w;
    }
    float inv = 1.f / l_tot;
    int qo = qi >> 2, g = qi & 3;
    int row  = b*QQ + qo;
    int head = kv*GG + g;
    #pragma unroll
    for (int j = 0; j < 8; j++)
        g_attnT[(size_t)(head*128 + d0 + j)*NTOK + row] = o[j] * inv;
}

// ---------------- 6. O GEMM partial (K-split, MLP=8 prefetch) ----------------
__global__ void k_gemm_o(const float* __restrict__ Wo) {
    __shared__ float4 hs[KCHUNK][8];
    int tx = threadIdx.x;
    int col = blockIdx.x * 128 + tx;
    int k0 = blockIdx.y * KCHUNK;
    const float* wcol = Wo + (size_t)k0 * 4096 + col;

    const float4* src = (const float4*)(g_attnT + (size_t)k0 * NTOK);
    float4* dst = &hs[0][0];
    #pragma unroll
    for (int i = 0; i < 8; i++) dst[tx + 128*i] = src[tx + 128*i];
    __syncthreads();

    unsigned long long acc[16];
    #pragma unroll
    for (int i = 0; i < 16; i++) acc[i] = 0ULL;

    #pragma unroll 1
    for (int kk = 0; kk < KCHUNK; kk += 8) {
        float w[8];
        #pragma unroll
        for (int u = 0; u < 8; u++) w[u] = wcol[(size_t)(kk + u) * 4096];
        #pragma unroll
        for (int u = 0; u < 8; u++) {
            unsigned long long w2 = pack2(w[u], w[u]);
            const ulonglong2* hp = (const ulonglong2*)&hs[kk + u][0];
            #pragma unroll
            for (int j = 0; j < 8; j++) {
                ulonglong2 h = hp[j];
                ffma2(acc[2*j],   h.x, w2);
                ffma2(acc[2*j+1], h.y, w2);
            }
        }
    }

    float* out = g_part_out + (size_t)blockIdx.y * NTOK * HH + col;
    #pragma unroll
    for (int i = 0; i < 16; i++) {
        out[(size_t)(2*i)   * HH] = lo2(acc[i]);
        out[(size_t)(2*i+1) * HH] = hi2(acc[i]);
    }
}

// ---------------- 7. reduce O partials -> output ----------------
__global__ void k_reduce_out(float* __restrict__ out) {
    int idx = blockIdx.x * 256 + threadIdx.x;
    float s = 0.f;
    #pragma unroll
    for (int i = 0; i < KSPLIT; i++)
        s += g_part_out[(size_t)i * NTOK * HH + idx];
    out[idx] = s;
}

// ---------------- launch ----------------
extern "C" void kernel_launch(void* const* d_in, const int* in_sizes, int n_in,
                              void* d_out, int out_size) {
    const float* hidden = (const float*)d_in[0];
    const float* cosb   = (const float*)d_in[1];
    const float* sinb   = (const float*)d_in[2];
    const float* Wq     = (const float*)d_in[3];
    const float* Wk     = (const float*)d_in[4];
    const float* Wv     = (const float*)d_in[5];
    const float* Wo     = (const float*)d_in[6];
    const float* Kc     = (const float*)d_in[7];
    const float* Vc     = (const float*)d_in[8];
    const int*   cls    = (const int*)d_in[9];
    int cap = in_sizes[7] / (BB * NKV * HD);   // 4100

    static int attr_set = 0;
    if (!attr_set) {
        cudaFuncSetAttribute(k_attn, cudaFuncAttributeMaxDynamicSharedMemorySize,
                             SMEM_ATTN_BYTES);
        attr_set = 1;
    }

    k_transpose  <<<512, 256>>>(hidden);
    k_gemm_qkv   <<<dim3(48, KSPLIT), 128>>>(Wq, Wk, Wv);
    k_reduce_rope<<<dim3(48, NTOK), 128>>>(cosb, sinb);
    k_attn       <<<dim3(NSPLIT, NKV, BB), 128, SMEM_ATTN_BYTES>>>(Kc, Vc, cls, cap);
    k_combine    <<<64, 256>>>();
    k_gemm_o     <<<dim3(32, KSPLIT), 128>>>(Wo);
    k_reduce_out <<<512, 256>>>((float*)d_out);
}